// round 16
// baseline (speedup 1.0000x reference)
#include <cuda_runtime.h>
#include <cuda_bf16.h>
#include <math.h>
#include <stdint.h>

#define BB 64
#define SS 512
#define DD 512
#define HH 1024
#define GG 4096   // 4*HH

// ---------------------------------------------------------------------------
// Device-global scratch. NEVER pass these as host-side kernel args (shadow
// symbol bug — R10 root cause). All kernels reference them device-side.
// ---------------------------------------------------------------------------
__device__ float g_gx[(size_t)BB * SS * GG];
__device__ __align__(256) __nv_bfloat16 g_whhi[(size_t)GG * HH];
__device__ __align__(256) __nv_bfloat16 g_whlo[(size_t)GG * HH];
__device__ __align__(256) __nv_bfloat16 g_wxhi[(size_t)GG * DD];
__device__ __align__(256) __nv_bfloat16 g_wxlo[(size_t)GG * DD];
__device__ __align__(256) __nv_bfloat16 g_xhi[(size_t)BB * SS * DD];
__device__ __align__(256) __nv_bfloat16 g_xlo[(size_t)BB * SS * DD];
__device__ __align__(256) __nv_bfloat16 g_hhi[2][BB * HH];
__device__ __align__(256) __nv_bfloat16 g_hlo[2][BB * HH];
__device__ unsigned g_bar;

// ---------------------------------------------------------------------------
// PTX helpers
// ---------------------------------------------------------------------------
__device__ __forceinline__ uint32_t smem_u32(const void* p) {
    uint32_t a;
    asm("{ .reg .u64 t; cvta.to.shared.u64 t, %1; cvt.u32.u64 %0, t; }" : "=r"(a) : "l"(p));
    return a;
}
__device__ __forceinline__ uint32_t lds32(uint32_t a) {
    uint32_t v;
    asm volatile("ld.shared.b32 %0, [%1];" : "=r"(v) : "r"(a));
    return v;
}
__device__ __forceinline__ uint4 ldg_cg(const void* p) {
    uint4 v;
    asm volatile("ld.global.cg.v4.u32 {%0,%1,%2,%3}, [%4];"
                 : "=r"(v.x), "=r"(v.y), "=r"(v.z), "=r"(v.w) : "l"(p));
    return v;
}
__device__ __forceinline__ void mma16816(float* d, const uint32_t* a, const uint32_t* b) {
    asm volatile(
        "mma.sync.aligned.m16n8k16.row.col.f32.bf16.bf16.f32 "
        "{%0,%1,%2,%3}, {%4,%5,%6,%7}, {%8,%9}, {%0,%1,%2,%3};"
        : "+f"(d[0]), "+f"(d[1]), "+f"(d[2]), "+f"(d[3])
        : "r"(a[0]), "r"(a[1]), "r"(a[2]), "r"(a[3]), "r"(b[0]), "r"(b[1]));
}

__device__ __forceinline__ float sigf(float x) { return 1.f / (1.f + __expf(-x)); }
__device__ __forceinline__ float tanhfast(float x) { return 1.f - 2.f / (__expf(2.f * x) + 1.f); }

// Global barrier across 128 co-resident CTAs (R12 version — proven).
__device__ __forceinline__ void gbar(int t) {
    __syncthreads();
    if (threadIdx.x == 0) {
        __threadfence();
        atomicAdd(&g_bar, 1u);
        const unsigned target = 128u * (unsigned)(t + 1);
        while (*(volatile unsigned*)&g_bar < target) {}
        __threadfence();
    }
    __syncthreads();
}

__global__ void bar_reset() { g_bar = 0u; }

// ---------------------------------------------------------------------------
// Splits (device-symbol writes ONLY; src via harness pointer)
// ---------------------------------------------------------------------------
__device__ __forceinline__ void split4(const float* src, size_t i,
                                       __nv_bfloat16* hi, __nv_bfloat16* lo) {
    float4 w = *(const float4*)(src + i);
    __nv_bfloat16 h0 = __float2bfloat16(w.x), h1 = __float2bfloat16(w.y);
    __nv_bfloat16 h2 = __float2bfloat16(w.z), h3 = __float2bfloat16(w.w);
    *(__nv_bfloat162*)(hi + i)     = __nv_bfloat162(h0, h1);
    *(__nv_bfloat162*)(hi + i + 2) = __nv_bfloat162(h2, h3);
    *(__nv_bfloat162*)(lo + i) =
        __nv_bfloat162(__float2bfloat16(w.x - __bfloat162float(h0)),
                       __float2bfloat16(w.y - __bfloat162float(h1)));
    *(__nv_bfloat162*)(lo + i + 2) =
        __nv_bfloat162(__float2bfloat16(w.z - __bfloat162float(h2)),
                       __float2bfloat16(w.w - __bfloat162float(h3)));
}
__global__ __launch_bounds__(256) void split_wh(const float* __restrict__ src) {
    split4(src, (size_t)blockIdx.x * 1024 + (size_t)threadIdx.x * 4, g_whhi, g_whlo);
}
__global__ __launch_bounds__(256) void split_wx(const float* __restrict__ src) {
    split4(src, (size_t)blockIdx.x * 1024 + (size_t)threadIdx.x * 4, g_wxhi, g_wxlo);
}
__global__ __launch_bounds__(256) void split_x(const float* __restrict__ src) {
    split4(src, (size_t)blockIdx.x * 1024 + (size_t)threadIdx.x * 4, g_xhi, g_xlo);
}

// ---------------------------------------------------------------------------
// Fragment loaders (HARDWARE-PROVEN mapping)
// ---------------------------------------------------------------------------
__device__ __forceinline__ void loadA_p(uint32_t base, int r0, int g, uint32_t ka,
                                        int pitch, uint32_t* a) {
    a[0] = lds32(base + (r0 + g) * pitch + ka);
    a[1] = lds32(base + (r0 + g + 8) * pitch + ka);
    a[2] = lds32(base + (r0 + g) * pitch + ka + 16);
    a[3] = lds32(base + (r0 + g + 8) * pitch + ka + 16);
}
__device__ __forceinline__ void loadB_p(uint32_t base, int nb, int g, uint32_t ka,
                                        int pitch, uint32_t* b) {
    b[0] = lds32(base + (nb + g) * pitch + ka);
    b[1] = lds32(base + (nb + g) * pitch + ka + 16);
}

// ===========================================================================
// gx GEMM via mma (proven in R12, unchanged)
// ===========================================================================
#define GXB 40960
#define GX_SMEM (2 * GXB)

struct GxFrag { uint4 xh[2], xl[2], wh[2], wl[2]; };

__device__ __forceinline__ void gx_ldg(GxFrag& f, int tid, int m0, int n0, int kc) {
#pragma unroll
    for (int i = 0; i < 2; i++) {
        int idx = tid + 256 * i, row = idx >> 2, k8 = idx & 3;
        size_t gox = (size_t)(m0 + row) * DD + (size_t)kc * 32 + (size_t)k8 * 8;
        size_t gow = (size_t)(n0 + row) * DD + (size_t)kc * 32 + (size_t)k8 * 8;
        f.xh[i] = *(const uint4*)(g_xhi + gox);
        f.xl[i] = *(const uint4*)(g_xlo + gox);
        f.wh[i] = *(const uint4*)(g_wxhi + gow);
        f.wl[i] = *(const uint4*)(g_wxlo + gow);
    }
}
__device__ __forceinline__ void gx_sts(const GxFrag& f, char* ab, int tid) {
#pragma unroll
    for (int i = 0; i < 2; i++) {
        int idx = tid + 256 * i, row = idx >> 2, k8 = idx & 3;
        char* d = ab + row * 80 + k8 * 16;
        *(uint4*)(d)         = f.xh[i];
        *(uint4*)(d + 10240) = f.xl[i];
        *(uint4*)(d + 20480) = f.wh[i];
        *(uint4*)(d + 30720) = f.wl[i];
    }
}

__device__ __forceinline__ void gx_compute(uint32_t ab, int lane, int wr, int wc,
                                           float (&acc)[2][8][4]) {
    const int g = lane >> 2, tig = lane & 3;
#pragma unroll
    for (int kk = 0; kk < 2; kk++) {
        const uint32_t ka = (uint32_t)((kk * 16 + 2 * tig) * 2);
        uint32_t ah0[4], ah1[4], al0[4], al1[4];
        loadA_p(ab, wr * 32, g, ka, 80, ah0);
        loadA_p(ab, wr * 32 + 16, g, ka, 80, ah1);
        loadA_p(ab + 10240, wr * 32, g, ka, 80, al0);
        loadA_p(ab + 10240, wr * 32 + 16, g, ka, 80, al1);
#pragma unroll
        for (int ng = 0; ng < 8; ng++) {
            uint32_t bh[2], bl[2];
            loadB_p(ab + 20480, wc * 64 + ng * 8, g, ka, 80, bh);
            loadB_p(ab + 30720, wc * 64 + ng * 8, g, ka, 80, bl);
            mma16816(acc[0][ng], ah0, bh);
            mma16816(acc[1][ng], ah1, bh);
            mma16816(acc[0][ng], ah0, bl);
            mma16816(acc[1][ng], ah1, bl);
            mma16816(acc[0][ng], al0, bh);
            mma16816(acc[1][ng], al1, bh);
        }
    }
}

__global__ __launch_bounds__(256) void gx_mma(const float* __restrict__ bx,
                                              const float* __restrict__ bh) {
    extern __shared__ __align__(128) char sm[];
    const uint32_t sb = smem_u32(sm);
    const int tid = threadIdx.x;
    const int wid = tid >> 5, lane = tid & 31;
    const int wr = wid & 3, wc = wid >> 2;
    const int m0 = blockIdx.y * 128, n0 = blockIdx.x * 128;

    float acc[2][8][4];
#pragma unroll
    for (int r = 0; r < 2; r++)
#pragma unroll
        for (int c = 0; c < 8; c++)
#pragma unroll
            for (int e = 0; e < 4; e++) acc[r][c][e] = 0.f;

    GxFrag fr;
    gx_ldg(fr, tid, m0, n0, 0);
    gx_sts(fr, sm, tid);
#pragma unroll 1
    for (int kc = 0; kc < 16; kc++) {
        const int s = kc & 1;
        __syncthreads();
        if (kc < 15) gx_ldg(fr, tid, m0, n0, kc + 1);
        gx_compute(sb + s * GXB, lane, wr, wc, acc);
        if (kc < 15) gx_sts(fr, sm + (s ^ 1) * GXB, tid);
    }

    const int r0 = m0 + wr * 32 + (lane >> 2);
    const int c0 = n0 + wc * 64 + 2 * (lane & 3);
#pragma unroll
    for (int ng = 0; ng < 8; ng++) {
        const int n = c0 + ng * 8;
        const float b0 = bx[n] + bh[n];
        const float b1 = bx[n + 1] + bh[n + 1];
#pragma unroll
        for (int rg = 0; rg < 2; rg++) {
            const int m = r0 + rg * 16;
            *(float2*)&g_gx[(size_t)m * GG + n] =
                make_float2(acc[rg][ng][0] + b0, acc[rg][ng][1] + b1);
            *(float2*)&g_gx[(size_t)(m + 8) * GG + n] =
                make_float2(acc[rg][ng][2] + b0, acc[rg][ng][3] + b1);
        }
    }
}

// ===========================================================================
// PERSISTENT scan: 128 CTAs x 256 thr (8 warps = 2/SMSP for latency hiding).
// Warp w -> batches [8w, 8w+8). Global barrier per step (R12, proven).
// smem: A_hi [0,73728), A_lo [73728,147456), B bufs @147456 + s*18432.
// ===========================================================================
#define A_LO_OFF 73728
#define B_OFF 147456
#define B_BUF 18432
#define SCAN_SMEM (B_OFF + 2 * B_BUF)   // 184320

struct BFrag { uint4 bh[2], bl[2]; };

__device__ __forceinline__ void ldgB(BFrag& f, int tid, int kc,
                                     const __nv_bfloat16* __restrict__ rh,
                                     const __nv_bfloat16* __restrict__ rl) {
#pragma unroll
    for (int i = 0; i < 2; i++) {
        int idx = tid + 256 * i, b = idx >> 3, k8 = idx & 7;
        size_t go = (size_t)b * HH + (size_t)kc * 64 + (size_t)k8 * 8;
        f.bh[i] = ldg_cg(rh + go);
        f.bl[i] = ldg_cg(rl + go);
    }
}
__device__ __forceinline__ void stsB(const BFrag& f, char* bb, int tid) {
#pragma unroll
    for (int i = 0; i < 2; i++) {
        int idx = tid + 256 * i, b = idx >> 3, k8 = idx & 7;
        char* d = bb + b * 144 + k8 * 16;
        *(uint4*)(d)        = f.bh[i];
        *(uint4*)(d + 9216) = f.bl[i];
    }
}

__device__ __forceinline__ void compute_chunk(uint32_t sb, int kc, int s,
                                              int lane, int wid,
                                              float (&acc)[2][4]) {
    const uint32_t aA = sb + kc * 4608;
    const uint32_t aB = sb + B_OFF + s * B_BUF;
    const int g = lane >> 2, tig = lane & 3;
#pragma unroll
    for (int kk = 0; kk < 4; kk++) {
        const uint32_t ka = (uint32_t)((kk * 16 + 2 * tig) * 2);
        uint32_t ah0[4], ah1[4], al0[4], al1[4], bh[2], bl[2];
        loadA_p(aA, 0, g, ka, 144, ah0);
        loadA_p(aA, 16, g, ka, 144, ah1);
        loadA_p(aA + A_LO_OFF, 0, g, ka, 144, al0);
        loadA_p(aA + A_LO_OFF, 16, g, ka, 144, al1);
        loadB_p(aB, wid * 8, g, ka, 144, bh);
        loadB_p(aB + 9216, wid * 8, g, ka, 144, bl);
        mma16816(acc[0], ah0, bh);
        mma16816(acc[1], ah1, bh);
        mma16816(acc[0], ah0, bl);
        mma16816(acc[1], ah1, bl);
        mma16816(acc[0], al0, bh);
        mma16816(acc[1], al1, bh);
    }
}

__global__ __launch_bounds__(256) void lstm_scan(float* __restrict__ out, int wf) {
    extern __shared__ __align__(128) char sm[];
    const uint32_t sb = smem_u32(sm);
    const int tid = threadIdx.x;
    const int wid = tid >> 5, lane = tid & 31;
    const int g = lane >> 2, q = lane & 3;
    const int j0 = blockIdx.x * 8;

    // A tile (Wh hi/lo, this CTA's 32 rows) resident in smem.
#pragma unroll 1
    for (int kc = 0; kc < 16; kc++) {
        int row = tid >> 3, k8 = tid & 7;
        size_t go = ((size_t)((row >> 3) * HH + j0 + (row & 7))) * HH
                  + (size_t)kc * 64 + (size_t)k8 * 8;
        char* d = sm + kc * 4608 + row * 144 + k8 * 16;
        *(uint4*)(d)            = *(const uint4*)(g_whhi + go);
        *(uint4*)(d + A_LO_OFF) = *(const uint4*)(g_whlo + go);
    }
    __syncthreads();

    // Thread's outputs: j = j0 + g; batches b0, b0+1 where b0 = 8*wid + 2q.
    const int j = j0 + g;
    const int b0 = wid * 8 + 2 * q;
    float creg[2];

    // ---- t = 0: gates = gx only ----
    {
        __nv_bfloat16* whp = g_hhi[0];
        __nv_bfloat16* wlp = g_hlo[0];
#pragma unroll
        for (int e = 0; e < 2; e++) {
            const int b = b0 + e;
            const size_t gb = (size_t)b * SS * GG + j;
            float iv = sigf(g_gx[gb]);
            float gv = tanhfast(g_gx[gb + 2 * HH]);
            float ov = sigf(g_gx[gb + 3 * HH]);
            float cn = iv * gv;
            float hn = ov * tanhfast(cn);
            creg[e] = cn;
            out[(size_t)b * SS * HH + j] = hn;
            __nv_bfloat16 hb = __float2bfloat16(hn);
            whp[b * HH + j] = hb;
            wlp[b * HH + j] = __float2bfloat16(hn - __bfloat162float(hb));
        }
    }
    gbar(0);

    // ---- t = 1 .. 511 ----
#pragma unroll 1
    for (int t = 1; t < SS; t++) {
        const __nv_bfloat16* rh = g_hhi[(t - 1) & 1];
        const __nv_bfloat16* rl = g_hlo[(t - 1) & 1];

        float acc[2][4];
#pragma unroll
        for (int r = 0; r < 2; r++)
#pragma unroll
            for (int e = 0; e < 4; e++) acc[r][e] = 0.f;

        // Prefetch epilogue gx values (static data) to hide DRAM latency.
        float pgx[2][4];
#pragma unroll
        for (int e = 0; e < 2; e++) {
            const size_t gb = ((size_t)(b0 + e) * SS + t) * (size_t)GG + j;
            pgx[e][0] = g_gx[gb];
            pgx[e][1] = g_gx[gb + HH];
            pgx[e][2] = g_gx[gb + 2 * HH];
            pgx[e][3] = g_gx[gb + 3 * HH];
        }

        BFrag fr;
        ldgB(fr, tid, 0, rh, rl);
        stsB(fr, sm + B_OFF, tid);
#pragma unroll 1
        for (int kc = 0; kc < 16; kc++) {
            const int s = kc & 1;
            __syncthreads();
            if (kc < 15) ldgB(fr, tid, kc + 1, rh, rl);
            compute_chunk(sb, kc, s, lane, wid, acc);
            if (kc < 15) stsB(fr, sm + B_OFF + (s ^ 1) * B_BUF, tid);
        }

        // Epilogue: i,f from acc[0]; g,o from acc[1]. c state in registers.
        __nv_bfloat16* whp = g_hhi[t & 1];
        __nv_bfloat16* wlp = g_hlo[t & 1];
#pragma unroll
        for (int e = 0; e < 2; e++) {
            const int b = b0 + e;
            float iv = acc[0][e]     + pgx[e][0];
            float fv = acc[0][2 + e] + pgx[e][1];
            float gv = acc[1][e]     + pgx[e][2];
            float ov = acc[1][2 + e] + pgx[e][3];
            iv = sigf(iv); fv = sigf(fv); gv = tanhfast(gv); ov = sigf(ov);
            const float cn = fmaf(fv, creg[e], iv * gv);
            const float hn = ov * tanhfast(cn);
            creg[e] = cn;
            out[((size_t)b * SS + t) * HH + j] = hn;
            __nv_bfloat16 hb = __float2bfloat16(hn);
            whp[b * HH + j] = hb;
            wlp[b * HH + j] = __float2bfloat16(hn - __bfloat162float(hb));
            if (wf && t == SS - 1) {
                out[(size_t)BB * SS * HH + (size_t)b * HH + j] = hn;
                out[(size_t)BB * SS * HH + (size_t)BB * HH + (size_t)b * HH + j] = cn;
            }
        }
        gbar(t);
    }
}

// ---------------------------------------------------------------------------
extern "C" void kernel_launch(void* const* d_in, const int* in_sizes, int n_in,
                              void* d_out, int out_size) {
    const float* x  = (const float*)d_in[0];
    const float* Wx = (const float*)d_in[1];
    const float* Wh = (const float*)d_in[2];
    const float* bx = (const float*)d_in[3];
    const float* bh = (const float*)d_in[4];
    float* out = (float*)d_out;

    const long long full = (long long)BB * SS * HH + 2LL * BB * HH;
    const int wf = ((long long)out_size >= full) ? 1 : 0;

    cudaFuncSetAttribute(lstm_scan, cudaFuncAttributeMaxDynamicSharedMemorySize,
                         SCAN_SMEM);
    cudaFuncSetAttribute(gx_mma, cudaFuncAttributeMaxDynamicSharedMemorySize,
                         GX_SMEM);

    bar_reset<<<1, 1>>>();
    split_wh<<<(GG * HH) / 1024, 256>>>(Wh);
    split_wx<<<(GG * DD) / 1024, 256>>>(Wx);
    split_x<<<(BB * SS * DD) / 1024, 256>>>(x);
    gx_mma<<<dim3(GG / 128, (BB * SS) / 128), 256, GX_SMEM>>>(bx, bh);
    lstm_scan<<<128, 256, SCAN_SMEM>>>(out, wf);
}

// round 17
// speedup vs baseline: 1.0954x; 1.0954x over previous
#include <cuda_runtime.h>
#include <cuda_bf16.h>
#include <math.h>
#include <stdint.h>

#define BB 64
#define SS 512
#define DD 512
#define HH 1024
#define GG 4096   // 4*HH

// ---------------------------------------------------------------------------
// Device-global scratch. NEVER pass these as host-side kernel args (shadow
// symbol bug — R10 root cause). All kernels reference them device-side.
// ---------------------------------------------------------------------------
__device__ float g_gx[(size_t)BB * SS * GG];
__device__ __align__(256) __nv_bfloat16 g_whhi[(size_t)GG * HH];
__device__ __align__(256) __nv_bfloat16 g_whlo[(size_t)GG * HH];
__device__ __align__(256) __nv_bfloat16 g_wxhi[(size_t)GG * DD];
__device__ __align__(256) __nv_bfloat16 g_wxlo[(size_t)GG * DD];
__device__ __align__(256) __nv_bfloat16 g_xhi[(size_t)BB * SS * DD];
__device__ __align__(256) __nv_bfloat16 g_xlo[(size_t)BB * SS * DD];
__device__ __align__(256) __nv_bfloat16 g_hhi[2][BB * HH];
__device__ __align__(256) __nv_bfloat16 g_hlo[2][BB * HH];
__device__ unsigned g_bar;

// ---------------------------------------------------------------------------
// PTX helpers
// ---------------------------------------------------------------------------
__device__ __forceinline__ uint32_t smem_u32(const void* p) {
    uint32_t a;
    asm("{ .reg .u64 t; cvta.to.shared.u64 t, %1; cvt.u32.u64 %0, t; }" : "=r"(a) : "l"(p));
    return a;
}
__device__ __forceinline__ uint32_t lds32(uint32_t a) {
    uint32_t v;
    asm volatile("ld.shared.b32 %0, [%1];" : "=r"(v) : "r"(a));
    return v;
}
__device__ __forceinline__ uint4 ldg_cg(const void* p) {
    uint4 v;
    asm volatile("ld.global.cg.v4.u32 {%0,%1,%2,%3}, [%4];"
                 : "=r"(v.x), "=r"(v.y), "=r"(v.z), "=r"(v.w) : "l"(p));
    return v;
}
__device__ __forceinline__ void mma16816(float* d, const uint32_t* a, const uint32_t* b) {
    asm volatile(
        "mma.sync.aligned.m16n8k16.row.col.f32.bf16.bf16.f32 "
        "{%0,%1,%2,%3}, {%4,%5,%6,%7}, {%8,%9}, {%0,%1,%2,%3};"
        : "+f"(d[0]), "+f"(d[1]), "+f"(d[2]), "+f"(d[3])
        : "r"(a[0]), "r"(a[1]), "r"(a[2]), "r"(a[3]), "r"(b[0]), "r"(b[1]));
}

__device__ __forceinline__ float sigf(float x) { return 1.f / (1.f + __expf(-x)); }
__device__ __forceinline__ float tanhfast(float x) { return 1.f - 2.f / (__expf(2.f * x) + 1.f); }

// Global barrier across 128 co-resident CTAs (proven).
__device__ __forceinline__ void gbar(int t) {
    __syncthreads();
    if (threadIdx.x == 0) {
        __threadfence();
        atomicAdd(&g_bar, 1u);
        const unsigned target = 128u * (unsigned)(t + 1);
        while (*(volatile unsigned*)&g_bar < target) {}
        __threadfence();
    }
    __syncthreads();
}

__global__ void bar_reset() { g_bar = 0u; }

// ---------------------------------------------------------------------------
// Splits (device-symbol writes ONLY; src via harness pointer)
// ---------------------------------------------------------------------------
__device__ __forceinline__ void split4(const float* src, size_t i,
                                       __nv_bfloat16* hi, __nv_bfloat16* lo) {
    float4 w = *(const float4*)(src + i);
    __nv_bfloat16 h0 = __float2bfloat16(w.x), h1 = __float2bfloat16(w.y);
    __nv_bfloat16 h2 = __float2bfloat16(w.z), h3 = __float2bfloat16(w.w);
    *(__nv_bfloat162*)(hi + i)     = __nv_bfloat162(h0, h1);
    *(__nv_bfloat162*)(hi + i + 2) = __nv_bfloat162(h2, h3);
    *(__nv_bfloat162*)(lo + i) =
        __nv_bfloat162(__float2bfloat16(w.x - __bfloat162float(h0)),
                       __float2bfloat16(w.y - __bfloat162float(h1)));
    *(__nv_bfloat162*)(lo + i + 2) =
        __nv_bfloat162(__float2bfloat16(w.z - __bfloat162float(h2)),
                       __float2bfloat16(w.w - __bfloat162float(h3)));
}
__global__ __launch_bounds__(256) void split_wh(const float* __restrict__ src) {
    split4(src, (size_t)blockIdx.x * 1024 + (size_t)threadIdx.x * 4, g_whhi, g_whlo);
}
__global__ __launch_bounds__(256) void split_wx(const float* __restrict__ src) {
    split4(src, (size_t)blockIdx.x * 1024 + (size_t)threadIdx.x * 4, g_wxhi, g_wxlo);
}
__global__ __launch_bounds__(256) void split_x(const float* __restrict__ src) {
    split4(src, (size_t)blockIdx.x * 1024 + (size_t)threadIdx.x * 4, g_xhi, g_xlo);
}

// ---------------------------------------------------------------------------
// Fragment loaders (HARDWARE-PROVEN mapping)
// ---------------------------------------------------------------------------
__device__ __forceinline__ void loadA_p(uint32_t base, int r0, int g, uint32_t ka,
                                        int pitch, uint32_t* a) {
    a[0] = lds32(base + (r0 + g) * pitch + ka);
    a[1] = lds32(base + (r0 + g + 8) * pitch + ka);
    a[2] = lds32(base + (r0 + g) * pitch + ka + 16);
    a[3] = lds32(base + (r0 + g + 8) * pitch + ka + 16);
}
__device__ __forceinline__ void loadB_p(uint32_t base, int nb, int g, uint32_t ka,
                                        int pitch, uint32_t* b) {
    b[0] = lds32(base + (nb + g) * pitch + ka);
    b[1] = lds32(base + (nb + g) * pitch + ka + 16);
}

// ===========================================================================
// gx GEMM via mma (proven in R12, unchanged)
// ===========================================================================
#define GXB 40960
#define GX_SMEM (2 * GXB)

struct GxFrag { uint4 xh[2], xl[2], wh[2], wl[2]; };

__device__ __forceinline__ void gx_ldg(GxFrag& f, int tid, int m0, int n0, int kc) {
#pragma unroll
    for (int i = 0; i < 2; i++) {
        int idx = tid + 256 * i, row = idx >> 2, k8 = idx & 3;
        size_t gox = (size_t)(m0 + row) * DD + (size_t)kc * 32 + (size_t)k8 * 8;
        size_t gow = (size_t)(n0 + row) * DD + (size_t)kc * 32 + (size_t)k8 * 8;
        f.xh[i] = *(const uint4*)(g_xhi + gox);
        f.xl[i] = *(const uint4*)(g_xlo + gox);
        f.wh[i] = *(const uint4*)(g_wxhi + gow);
        f.wl[i] = *(const uint4*)(g_wxlo + gow);
    }
}
__device__ __forceinline__ void gx_sts(const GxFrag& f, char* ab, int tid) {
#pragma unroll
    for (int i = 0; i < 2; i++) {
        int idx = tid + 256 * i, row = idx >> 2, k8 = idx & 3;
        char* d = ab + row * 80 + k8 * 16;
        *(uint4*)(d)         = f.xh[i];
        *(uint4*)(d + 10240) = f.xl[i];
        *(uint4*)(d + 20480) = f.wh[i];
        *(uint4*)(d + 30720) = f.wl[i];
    }
}

__device__ __forceinline__ void gx_compute(uint32_t ab, int lane, int wr, int wc,
                                           float (&acc)[2][8][4]) {
    const int g = lane >> 2, tig = lane & 3;
#pragma unroll
    for (int kk = 0; kk < 2; kk++) {
        const uint32_t ka = (uint32_t)((kk * 16 + 2 * tig) * 2);
        uint32_t ah0[4], ah1[4], al0[4], al1[4];
        loadA_p(ab, wr * 32, g, ka, 80, ah0);
        loadA_p(ab, wr * 32 + 16, g, ka, 80, ah1);
        loadA_p(ab + 10240, wr * 32, g, ka, 80, al0);
        loadA_p(ab + 10240, wr * 32 + 16, g, ka, 80, al1);
#pragma unroll
        for (int ng = 0; ng < 8; ng++) {
            uint32_t bh[2], bl[2];
            loadB_p(ab + 20480, wc * 64 + ng * 8, g, ka, 80, bh);
            loadB_p(ab + 30720, wc * 64 + ng * 8, g, ka, 80, bl);
            mma16816(acc[0][ng], ah0, bh);
            mma16816(acc[1][ng], ah1, bh);
            mma16816(acc[0][ng], ah0, bl);
            mma16816(acc[1][ng], ah1, bl);
            mma16816(acc[0][ng], al0, bh);
            mma16816(acc[1][ng], al1, bh);
        }
    }
}

__global__ __launch_bounds__(256) void gx_mma(const float* __restrict__ bx,
                                              const float* __restrict__ bh) {
    extern __shared__ __align__(128) char sm[];
    const uint32_t sb = smem_u32(sm);
    const int tid = threadIdx.x;
    const int wid = tid >> 5, lane = tid & 31;
    const int wr = wid & 3, wc = wid >> 2;
    const int m0 = blockIdx.y * 128, n0 = blockIdx.x * 128;

    float acc[2][8][4];
#pragma unroll
    for (int r = 0; r < 2; r++)
#pragma unroll
        for (int c = 0; c < 8; c++)
#pragma unroll
            for (int e = 0; e < 4; e++) acc[r][c][e] = 0.f;

    GxFrag fr;
    gx_ldg(fr, tid, m0, n0, 0);
    gx_sts(fr, sm, tid);
#pragma unroll 1
    for (int kc = 0; kc < 16; kc++) {
        const int s = kc & 1;
        __syncthreads();
        if (kc < 15) gx_ldg(fr, tid, m0, n0, kc + 1);
        gx_compute(sb + s * GXB, lane, wr, wc, acc);
        if (kc < 15) gx_sts(fr, sm + (s ^ 1) * GXB, tid);
    }

    const int r0 = m0 + wr * 32 + (lane >> 2);
    const int c0 = n0 + wc * 64 + 2 * (lane & 3);
#pragma unroll
    for (int ng = 0; ng < 8; ng++) {
        const int n = c0 + ng * 8;
        const float b0 = bx[n] + bh[n];
        const float b1 = bx[n + 1] + bh[n + 1];
#pragma unroll
        for (int rg = 0; rg < 2; rg++) {
            const int m = r0 + rg * 16;
            *(float2*)&g_gx[(size_t)m * GG + n] =
                make_float2(acc[rg][ng][0] + b0, acc[rg][ng][1] + b1);
            *(float2*)&g_gx[(size_t)(m + 8) * GG + n] =
                make_float2(acc[rg][ng][2] + b0, acc[rg][ng][3] + b1);
        }
    }
}

// ===========================================================================
// PERSISTENT scan: 128 CTAs x 256 thr.
// NEW: 16x16 warp tiles over a GATE-INTERLEAVED resident A layout:
//   smem tile row r = mt*16 + gate*4 + jl  (mt=r>>4, gate=(r>>2)&3, jl=r&3)
//   global Wh row   = gate*HH + j0 + mt*4 + jl
// Warp wid: mt = wid&1 (j group), nb = (wid>>1)*16 (batch group).
// Split accumulators (hh/hl/lh) break mma dependency chains.
// Epilogue: shfl_xor(16) reunites gate pairs {i,g}/{f,o}; thread -> 2 (b,j).
// ===========================================================================
#define A_LO_OFF 73728
#define B_OFF 147456
#define B_BUF 18432
#define SCAN_SMEM (B_OFF + 2 * B_BUF)   // 184320

struct BFrag { uint4 bh[2], bl[2]; };

__device__ __forceinline__ void ldgB(BFrag& f, int tid, int kc,
                                     const __nv_bfloat16* __restrict__ rh,
                                     const __nv_bfloat16* __restrict__ rl) {
#pragma unroll
    for (int i = 0; i < 2; i++) {
        int idx = tid + 256 * i, b = idx >> 3, k8 = idx & 7;
        size_t go = (size_t)b * HH + (size_t)kc * 64 + (size_t)k8 * 8;
        f.bh[i] = ldg_cg(rh + go);
        f.bl[i] = ldg_cg(rl + go);
    }
}
__device__ __forceinline__ void stsB(const BFrag& f, char* bb, int tid) {
#pragma unroll
    for (int i = 0; i < 2; i++) {
        int idx = tid + 256 * i, b = idx >> 3, k8 = idx & 7;
        char* d = bb + b * 144 + k8 * 16;
        *(uint4*)(d)        = f.bh[i];
        *(uint4*)(d + 9216) = f.bl[i];
    }
}

__device__ __forceinline__ void compute_chunk(uint32_t sb, int kc, int s,
                                              int gg, int tig, int mt, int nb,
                                              float (&acc)[3][2][4]) {
    const uint32_t aA = sb + kc * 4608 + mt * (16 * 144);
    const uint32_t aB = sb + B_OFF + s * B_BUF;
#pragma unroll
    for (int kk = 0; kk < 4; kk++) {
        const uint32_t ka = (uint32_t)((kk * 16 + 2 * tig) * 2);
        uint32_t ah[4], al[4], bh0[2], bh1[2], bl0[2], bl1[2];
        loadA_p(aA, 0, gg, ka, 144, ah);
        loadA_p(aA + A_LO_OFF, 0, gg, ka, 144, al);
        loadB_p(aB, nb, gg, ka, 144, bh0);
        loadB_p(aB, nb + 8, gg, ka, 144, bh1);
        loadB_p(aB + 9216, nb, gg, ka, 144, bl0);
        loadB_p(aB + 9216, nb + 8, gg, ka, 144, bl1);
        // 6 independent accumulator chains:
        mma16816(acc[0][0], ah, bh0);  mma16816(acc[0][1], ah, bh1);  // hh
        mma16816(acc[1][0], ah, bl0);  mma16816(acc[1][1], ah, bl1);  // hl
        mma16816(acc[2][0], al, bh0);  mma16816(acc[2][1], al, bh1);  // lh
    }
}

__global__ __launch_bounds__(256) void lstm_scan(float* __restrict__ out, int wf) {
    extern __shared__ __align__(128) char sm[];
    const uint32_t sb = smem_u32(sm);
    const int tid = threadIdx.x;
    const int wid = tid >> 5, lane = tid & 31;
    const int gg = lane >> 2, tig = lane & 3;
    const int g0 = gg >> 2;               // 0: thread holds {i,g}; 1: {f,o}
    const int jl = gg & 3;
    const int mt = wid & 1;
    const int nb = (wid >> 1) * 16;
    const int j0 = blockIdx.x * 8;
    const int j = j0 + mt * 4 + jl;

    int bc[2];
#pragma unroll
    for (int c = 0; c < 2; c++) bc[c] = nb + c * 8 + 2 * tig + g0;

    // A tile resident, GATE-INTERLEAVED: tile row = mt*16 + gate*4 + jl.
#pragma unroll 1
    for (int kc = 0; kc < 16; kc++) {
        int row = tid >> 3, k8 = tid & 7;
        int gate = (row >> 2) & 3, mtr = row >> 4, jlr = row & 3;
        size_t go = ((size_t)gate * HH + j0 + mtr * 4 + jlr) * HH
                  + (size_t)kc * 64 + (size_t)k8 * 8;
        char* d = sm + kc * 4608 + row * 144 + k8 * 16;
        *(uint4*)(d)            = *(const uint4*)(g_whhi + go);
        *(uint4*)(d + A_LO_OFF) = *(const uint4*)(g_whlo + go);
    }
    __syncthreads();

    float creg[2];

    // ---- t = 0: gates = gx only ----
    {
        __nv_bfloat16* whp = g_hhi[0];
        __nv_bfloat16* wlp = g_hlo[0];
#pragma unroll
        for (int c = 0; c < 2; c++) {
            const int b = bc[c];
            const size_t gb = (size_t)b * SS * GG + j;
            float iv = sigf(g_gx[gb]);
            float gv = tanhfast(g_gx[gb + 2 * HH]);
            float ov = sigf(g_gx[gb + 3 * HH]);
            float cn = iv * gv;
            float hn = ov * tanhfast(cn);
            creg[c] = cn;
            out[(size_t)b * SS * HH + j] = hn;
            __nv_bfloat16 hb = __float2bfloat16(hn);
            whp[b * HH + j] = hb;
            wlp[b * HH + j] = __float2bfloat16(hn - __bfloat162float(hb));
        }
    }
    gbar(0);

    // ---- t = 1 .. 511 ----
#pragma unroll 1
    for (int t = 1; t < SS; t++) {
        const __nv_bfloat16* rh = g_hhi[(t - 1) & 1];
        const __nv_bfloat16* rl = g_hlo[(t - 1) & 1];

        float acc[3][2][4];
#pragma unroll
        for (int p = 0; p < 3; p++)
#pragma unroll
            for (int c = 0; c < 2; c++)
#pragma unroll
                for (int e = 0; e < 4; e++) acc[p][c][e] = 0.f;

        // Prefetch epilogue gx values (DRAM) early.
        float pgx[2][4];
#pragma unroll
        for (int c = 0; c < 2; c++) {
            const size_t gb = ((size_t)bc[c] * SS + t) * (size_t)GG + j;
            pgx[c][0] = g_gx[gb];
            pgx[c][1] = g_gx[gb + HH];
            pgx[c][2] = g_gx[gb + 2 * HH];
            pgx[c][3] = g_gx[gb + 3 * HH];
        }

        BFrag fr;
        ldgB(fr, tid, 0, rh, rl);
        stsB(fr, sm + B_OFF, tid);
#pragma unroll 1
        for (int kc = 0; kc < 16; kc++) {
            const int s = kc & 1;
            __syncthreads();
            if (kc < 15) ldgB(fr, tid, kc + 1, rh, rl);
            compute_chunk(sb, kc, s, gg, tig, mt, nb, acc);
            if (kc < 15) stsB(fr, sm + B_OFF + (s ^ 1) * B_BUF, tid);
        }

        // Combine passes, exchange gate pairs via shfl_xor(16).
        float accf[2][4], xa[2][4];
#pragma unroll
        for (int c = 0; c < 2; c++)
#pragma unroll
            for (int e = 0; e < 4; e++) {
                accf[c][e] = acc[0][c][e] + acc[1][c][e] + acc[2][c][e];
                xa[c][e] = __shfl_xor_sync(0xffffffffu, accf[c][e], 16);
            }

        __nv_bfloat16* whp = g_hhi[t & 1];
        __nv_bfloat16* wlp = g_hlo[t & 1];
#pragma unroll
        for (int c = 0; c < 2; c++) {
            const int b = bc[c];
            float iv = g0 ? xa[c][1]   : accf[c][0];
            float fv = g0 ? accf[c][1] : xa[c][0];
            float gv = g0 ? xa[c][3]   : accf[c][2];
            float ov = g0 ? accf[c][3] : xa[c][2];
            iv = sigf(iv + pgx[c][0]);
            fv = sigf(fv + pgx[c][1]);
            gv = tanhfast(gv + pgx[c][2]);
            ov = sigf(ov + pgx[c][3]);
            const float cn = fmaf(fv, creg[c], iv * gv);
            const float hn = ov * tanhfast(cn);
            creg[c] = cn;
            out[((size_t)b * SS + t) * HH + j] = hn;
            __nv_bfloat16 hb = __float2bfloat16(hn);
            whp[b * HH + j] = hb;
            wlp[b * HH + j] = __float2bfloat16(hn - __bfloat162float(hb));
            if (wf && t == SS - 1) {
                out[(size_t)BB * SS * HH + (size_t)b * HH + j] = hn;
                out[(size_t)BB * SS * HH + (size_t)BB * HH + (size_t)b * HH + j] = cn;
            }
        }
        gbar(t);
    }
}

// ---------------------------------------------------------------------------
extern "C" void kernel_launch(void* const* d_in, const int* in_sizes, int n_in,
                              void* d_out, int out_size) {
    const float* x  = (const float*)d_in[0];
    const float* Wx = (const float*)d_in[1];
    const float* Wh = (const float*)d_in[2];
    const float* bx = (const float*)d_in[3];
    const float* bh = (const float*)d_in[4];
    float* out = (float*)d_out;

    const long long full = (long long)BB * SS * HH + 2LL * BB * HH;
    const int wf = ((long long)out_size >= full) ? 1 : 0;

    cudaFuncSetAttribute(lstm_scan, cudaFuncAttributeMaxDynamicSharedMemorySize,
                         SCAN_SMEM);
    cudaFuncSetAttribute(gx_mma, cudaFuncAttributeMaxDynamicSharedMemorySize,
                         GX_SMEM);

    bar_reset<<<1, 1>>>();
    split_wh<<<(GG * HH) / 1024, 256>>>(Wh);
    split_wx<<<(GG * DD) / 1024, 256>>>(Wx);
    split_x<<<(BB * SS * DD) / 1024, 256>>>(x);
    gx_mma<<<dim3(GG / 128, (BB * SS) / 128), 256, GX_SMEM>>>(bx, bh);
    lstm_scan<<<128, 256, SCAN_SMEM>>>(out, wf);
}